// round 8
// baseline (speedup 1.0000x reference)
#include <cuda_runtime.h>
#include <cuda_bf16.h>
#include <cstdint>
#include <cstddef>

#define DI 128
#define DO 64
#define NMAX 100000

// B image layout: [128 n][136 k-pitch] bf16 (272B row pitch)
#define BPITCH 136

// ---------------------------------------------------------------------------
// Scratch
// ---------------------------------------------------------------------------
__device__ __align__(16) float g_scratch[6 * (size_t)NMAX * DO + 6 * (size_t)NMAX];
__device__ __align__(16) __nv_bfloat16 g_B1hi[128 * BPITCH], g_B1lo[128 * BPITCH];
__device__ __align__(16) __nv_bfloat16 g_B2hi[128 * BPITCH], g_B2lo[128 * BPITCH];

__device__ __forceinline__ uint32_t smem_u32(const void* p) {
    uint32_t a;
    asm("{ .reg .u64 t; cvta.to.shared.u64 t, %1; cvt.u32.u64 %0, t; }"
        : "=r"(a) : "l"(p));
    return a;
}

__device__ __forceinline__ void ldm_x4(uint32_t* r, uint32_t addr) {
    asm volatile("ldmatrix.sync.aligned.m8n8.x4.shared.b16 {%0,%1,%2,%3}, [%4];"
                 : "=r"(r[0]), "=r"(r[1]), "=r"(r[2]), "=r"(r[3]) : "r"(addr));
}

__device__ __forceinline__ void mma_bf16(float* c, const uint32_t* a,
                                         uint32_t b0, uint32_t b1) {
    asm volatile("mma.sync.aligned.m16n8k16.row.col.f32.bf16.bf16.f32 "
                 "{%0,%1,%2,%3}, {%4,%5,%6,%7}, {%8,%9}, {%0,%1,%2,%3};"
                 : "+f"(c[0]), "+f"(c[1]), "+f"(c[2]), "+f"(c[3])
                 : "r"(a[0]), "r"(a[1]), "r"(a[2]), "r"(a[3]),
                   "r"(b0), "r"(b1));
}

__device__ __forceinline__ void split2(float x, float y, uint32_t& hi, uint32_t& lo) {
    __nv_bfloat162 h = __floats2bfloat162_rn(x, y);
    __nv_bfloat162 l = __floats2bfloat162_rn(x - __bfloat162float(h.x),
                                             y - __bfloat162float(h.y));
    hi = *(uint32_t*)&h;
    lo = *(uint32_t*)&l;
}

// SMEM layout (bytes): a-vec (256B) + B hi/lo slices (64 rows x 272B each)
#define XPITCH 272
#define OFF_A    0
#define OFF_BHI  256
#define OFF_BLO  (OFF_BHI + 64 * XPITCH)
#define SMEM_TOT (OFF_BLO + 64 * XPITCH)   // 35072

// ---------------------------------------------------------------------------
// Arg bundles
// ---------------------------------------------------------------------------
struct GA {
    const float* X;
    const __nv_bfloat16* Bhi;
    const __nv_bfloat16* Blo;
    float* Ya; float* Yb;
    const float* aA; const float* aB;
    float* sA; float* sB;
    int N;
};
struct EA {
    const int* src; const int* tgt;
    const float* ss; const float* ts;
    const float4* sx4; float4* msg4; float* den;
    int E;
};

// ---------------------------------------------------------------------------
// Prep (merged): B[n][k] = Wa[k][n] (n<64) else Wb[k][n-64], split bf16 hi/lo.
// ---------------------------------------------------------------------------
__global__ void pre_w_k(const float* __restrict__ Wa1, const float* __restrict__ Wb1,
                        __nv_bfloat16* __restrict__ B1hi, __nv_bfloat16* __restrict__ B1lo,
                        const float* __restrict__ Wa2, const float* __restrict__ Wb2,
                        __nv_bfloat16* __restrict__ B2hi, __nv_bfloat16* __restrict__ B2lo) {
    int which = blockIdx.x >> 6;
    int idx = (blockIdx.x & 63) * 256 + threadIdx.x;
    const float* Wa = which ? Wa2 : Wa1;
    const float* Wb = which ? Wb2 : Wb1;
    __nv_bfloat16* Bhi = which ? B2hi : B1hi;
    __nv_bfloat16* Blo = which ? B2lo : B1lo;
    int n = idx >> 7, k = idx & 127;
    float w = (n < 64) ? Wa[k * 64 + n] : Wb[k * 64 + (n - 64)];
    __nv_bfloat16 hi = __float2bfloat16(w);
    __nv_bfloat16 lo = __float2bfloat16(w - __bfloat162float(hi));
    Bhi[n * BPITCH + k] = hi;
    Blo[n * BPITCH + k] = lo;
}

// ---------------------------------------------------------------------------
// zero kernel
// ---------------------------------------------------------------------------
__global__ void zero_k(float* __restrict__ p, size_t nf) {
    size_t i = ((size_t)blockIdx.x * blockDim.x + threadIdx.x) * 4;
    if (i + 4 <= nf) {
        *(float4*)(p + i) = make_float4(0.f, 0.f, 0.f, 0.f);
    } else {
        for (; i < nf; i++) p[i] = 0.f;
    }
}

// ---------------------------------------------------------------------------
// Merged HMMA GEMM. CTA tile: 128 rows x 64 cols (one output matrix).
// blockIdx low bit picks the col-half (Ya or Yb). Warp tile 32x32 (4M x 2N).
// Split-bf16: D = Xhi*Bhi + Xhi*Blo + Xlo*Bhi (fp32 acc). A from gmem.
// Score partials combined across the 2 col-group warps via atomicAdd
// (score arrays pre-zeroed).
// ---------------------------------------------------------------------------
__global__ __launch_bounds__(256, 3)
void gemm_tc(GA g1, GA g2, int nb1)
{
    extern __shared__ char sm[];
    const uint32_t sb = smem_u32(sm);
    const int tid = threadIdx.x, wid = tid >> 5, lane = tid & 31;

    const int half = blockIdx.x & 1;
    const int tb = blockIdx.x >> 1;
    const bool first = tb < nb1;
    const GA g = first ? g1 : g2;
    const int row0 = (first ? tb : tb - nb1) * 128;

    // Copy this half's 64-row B slice (hi+lo) into smem
    {
        const float4* bh = (const float4*)g.Bhi + half * 1088;
        const float4* bl = (const float4*)g.Blo + half * 1088;
        float4* sh = (float4*)(sm + OFF_BHI);
        float4* sl = (float4*)(sm + OFF_BLO);
#pragma unroll
        for (int i = 0; i < 5; i++) {
            int idx = i * 256 + tid;
            if (idx < 1088) {
                sh[idx] = bh[idx];
                sl[idx] = bl[idx];
            }
        }
    }
    if (tid < 64)
        ((float*)(sm + OFF_A))[tid] = __ldg(&(half ? g.aB : g.aA)[tid]);

    const int wm = wid & 3, wn2 = wid >> 2;   // wn2 in {0,1}: 32-col group
    const int c0 = (lane & 3) * 2;

    const int rb = row0 + wm * 32 + (lane >> 2);
    int rows[4] = {rb, rb + 8, rb + 16, rb + 24};
    bool ok[4];
    const float* xp[4];
#pragma unroll
    for (int m = 0; m < 4; m++) {
        ok[m] = rows[m] < g.N;
        xp[m] = g.X + (size_t)(ok[m] ? rows[m] : 0) * DI + c0;
    }

    __syncthreads();

    // Accumulators: c[mtile*4 + ntile][4]; mtile 0..1, ntile 0..3 (8 cols each)
    float c[8][4];
#pragma unroll
    for (int j = 0; j < 8; j++)
#pragma unroll
        for (int q = 0; q < 4; q++) c[j][q] = 0.f;

    const int brow = (lane & 7) + ((lane >> 4) & 1) * 8;
    const int bkk  = ((lane >> 3) & 1) * 8;
    const uint32_t bbase = sb + (wn2 * 32 + brow) * XPITCH + bkk * 2;

#pragma unroll
    for (int s = 0; s < 8; s++) {
        const int ks = s * 16;
        float2 v[8];
#pragma unroll
        for (int m = 0; m < 4; m++) {
            v[m]     = ok[m] ? *(const float2*)(xp[m] + ks)     : make_float2(0.f, 0.f);
            v[m + 4] = ok[m] ? *(const float2*)(xp[m] + ks + 8) : make_float2(0.f, 0.f);
        }
        uint32_t ah0[4], al0[4], ah1[4], al1[4];
        split2(v[0].x, v[0].y, ah0[0], al0[0]);
        split2(v[1].x, v[1].y, ah0[1], al0[1]);
        split2(v[4].x, v[4].y, ah0[2], al0[2]);
        split2(v[5].x, v[5].y, ah0[3], al0[3]);
        split2(v[2].x, v[2].y, ah1[0], al1[0]);
        split2(v[3].x, v[3].y, ah1[1], al1[1]);
        split2(v[6].x, v[6].y, ah1[2], al1[2]);
        split2(v[7].x, v[7].y, ah1[3], al1[3]);

#pragma unroll
        for (int p = 0; p < 2; p++) {
            uint32_t bh[4], bl[4];
            uint32_t boff = (uint32_t)(p * 16) * XPITCH + ks * 2;
            ldm_x4(bh, bbase + OFF_BHI + boff);
            ldm_x4(bl, bbase + OFF_BLO + boff);
            // mtile 0
            mma_bf16(c[2 * p],     ah0, bh[0], bh[1]);
            mma_bf16(c[2 * p],     ah0, bl[0], bl[1]);
            mma_bf16(c[2 * p],     al0, bh[0], bh[1]);
            mma_bf16(c[2 * p + 1], ah0, bh[2], bh[3]);
            mma_bf16(c[2 * p + 1], ah0, bl[2], bl[3]);
            mma_bf16(c[2 * p + 1], al0, bh[2], bh[3]);
            // mtile 1
            mma_bf16(c[4 + 2 * p],     ah1, bh[0], bh[1]);
            mma_bf16(c[4 + 2 * p],     ah1, bl[0], bl[1]);
            mma_bf16(c[4 + 2 * p],     al1, bh[0], bh[1]);
            mma_bf16(c[4 + 2 * p + 1], ah1, bh[2], bh[3]);
            mma_bf16(c[4 + 2 * p + 1], ah1, bl[2], bl[3]);
            mma_bf16(c[4 + 2 * p + 1], al1, bh[2], bh[3]);
        }
    }

    // Epilogue for this half: Y = half? Yb : Ya, score -> sB/sA via atomicAdd
    const float* av = (const float*)(sm + OFF_A);
    float* Y    = half ? g.Yb : g.Ya;
    float* sOut = half ? g.sB : g.sA;

    float sc[4] = {0.f, 0.f, 0.f, 0.f};
#pragma unroll
    for (int n = 0; n < 4; n++) {
        int col = wn2 * 32 + n * 8 + c0;
        float a0 = av[col], a1 = av[col + 1];
        sc[0] += c[n][0] * a0 + c[n][1] * a1;
        sc[1] += c[n][2] * a0 + c[n][3] * a1;
        sc[2] += c[4 + n][0] * a0 + c[4 + n][1] * a1;
        sc[3] += c[4 + n][2] * a0 + c[4 + n][3] * a1;
        if (ok[0]) *(float2*)&Y[(size_t)rows[0] * DO + col] = make_float2(c[n][0], c[n][1]);
        if (ok[1]) *(float2*)&Y[(size_t)rows[1] * DO + col] = make_float2(c[n][2], c[n][3]);
        if (ok[2]) *(float2*)&Y[(size_t)rows[2] * DO + col] = make_float2(c[4 + n][0], c[4 + n][1]);
        if (ok[3]) *(float2*)&Y[(size_t)rows[3] * DO + col] = make_float2(c[4 + n][2], c[4 + n][3]);
    }
#pragma unroll
    for (int o = 1; o <= 2; o <<= 1) {
#pragma unroll
        for (int m = 0; m < 4; m++) sc[m] += __shfl_xor_sync(0xffffffffu, sc[m], o);
    }
    if ((lane & 3) == 0) {
#pragma unroll
        for (int m = 0; m < 4; m++)
            if (ok[m]) atomicAdd(&sOut[rows[m]], sc[m]);
    }
}

// ---------------------------------------------------------------------------
// Merged fused edge scatter (R6 version): 16 lanes per edge, 4 edges/group.
// ---------------------------------------------------------------------------
__global__ __launch_bounds__(256) void edge_k(EA e1, EA e2, int nb1)
{
    const bool first = blockIdx.x < (unsigned)nb1;
    const EA a = first ? e1 : e2;
    const int bb = first ? blockIdx.x : blockIdx.x - nb1;

    int g = bb * 16 + (threadIdx.x >> 4);
    int lane = threadIdx.x & 15;
    int e0 = g * 4;
    if (e0 >= a.E) return;
    int n = a.E - e0; if (n > 4) n = 4;

    int s[4], t[4];
#pragma unroll
    for (int j = 0; j < 4; j++) {
        int e = e0 + (j < n ? j : 0);
        s[j] = __ldg(&a.src[e]);
        t[j] = __ldg(&a.tgt[e]);
    }
    float att[4];
#pragma unroll
    for (int j = 0; j < 4; j++) {
        float scr = __ldg(&a.ss[s[j]]) + __ldg(&a.ts[t[j]]);
        float sl = scr >= 0.f ? scr : 0.2f * scr;
        att[j] = expf(sl);
    }
    float4 v[4];
#pragma unroll
    for (int j = 0; j < 4; j++) v[j] = __ldg(&a.sx4[(size_t)s[j] * 16 + lane]);
#pragma unroll
    for (int j = 0; j < 4; j++) {
        if (j < n) {
            float4* p = &a.msg4[(size_t)t[j] * 16 + lane];
            asm volatile("red.global.add.v4.f32 [%0], {%1,%2,%3,%4};"
                         :: "l"(p), "f"(v[j].x * att[j]), "f"(v[j].y * att[j]),
                            "f"(v[j].z * att[j]), "f"(v[j].w * att[j]) : "memory");
            if (lane == 0) atomicAdd(&a.den[t[j]], att[j]);
        }
    }
}

// ---------------------------------------------------------------------------
// Merged finalize: out = tx + msg / (den + eps)
// ---------------------------------------------------------------------------
__global__ __launch_bounds__(256) void final_k(
    const float4* __restrict__ txu, const float4* __restrict__ msgu,
    const float* __restrict__ denu,
    const float4* __restrict__ txi, const float4* __restrict__ msgi,
    const float* __restrict__ deni,
    float4* __restrict__ out, int n4u, int n4tot)
{
    int i = blockIdx.x * blockDim.x + threadIdx.x;
    if (i >= n4tot) return;
    const float4* txp; const float4* msg; const float* den;
    int li;
    if (i < n4u) { txp = txu; msg = msgu; den = denu; li = i; }
    else         { txp = txi; msg = msgi; den = deni; li = i - n4u; }
    int node = li >> 4;
    float inv = 1.f / (den[node] + 1e-6f);
    float4 m = msg[li];
    float4 t = txp[li];
    out[i] = make_float4(t.x + m.x * inv, t.y + m.y * inv,
                         t.z + m.z * inv, t.w + m.w * inv);
}

// ---------------------------------------------------------------------------
extern "C" void kernel_launch(void* const* d_in, const int* in_sizes, int n_in,
                              void* d_out, int out_size)
{
    const float* x_user   = (const float*)d_in[0];
    const float* x_item   = (const float*)d_in[1];
    const float* W_ui_src = (const float*)d_in[2];
    const float* W_ui_tgt = (const float*)d_in[3];
    const float* W_iu_src = (const float*)d_in[4];
    const float* W_iu_tgt = (const float*)d_in[5];
    const float* a_ui     = (const float*)d_in[6];
    const float* a_iu     = (const float*)d_in[7];
    const int*   edge_ui  = (const int*)d_in[8];
    const int*   edge_iu  = (const int*)d_in[9];
    float* out = (float*)d_out;

    const int Nu  = in_sizes[0] / DI;
    const int Ni  = in_sizes[1] / DI;
    const int Eui = in_sizes[8] / 2;
    const int Eiu = in_sizes[9] / 2;

    float* base = nullptr;
    cudaGetSymbolAddress((void**)&base, g_scratch);
    __nv_bfloat16 *B1hi, *B1lo, *B2hi, *B2lo;
    cudaGetSymbolAddress((void**)&B1hi, g_B1hi);
    cudaGetSymbolAddress((void**)&B1lo, g_B1lo);
    cudaGetSymbolAddress((void**)&B2hi, g_B2hi);
    cudaGetSymbolAddress((void**)&B2lo, g_B2lo);

    float* s = base;
    float* sx_ui  = s; s += (size_t)Nu * DO;
    float* tx_iu  = s; s += (size_t)Nu * DO;
    float* sx_iu  = s; s += (size_t)Ni * DO;
    float* tx_ui  = s; s += (size_t)Ni * DO;
    float* msg_ui = s; s += (size_t)Ni * DO;
    float* msg_iu = s; s += (size_t)Nu * DO;
    float* den_ui = s; s += Ni;
    float* den_iu = s; s += Nu;
    float* ss_ui  = s; s += Nu;
    float* ts_ui  = s; s += Ni;
    float* ss_iu  = s; s += Ni;
    float* ts_iu  = s; s += Nu;

    cudaFuncSetAttribute(gemm_tc, cudaFuncAttributeMaxDynamicSharedMemorySize, SMEM_TOT);

    // Zero msg + den + score arrays (contiguous from msg_ui)
    {
        size_t zf = (size_t)(Ni + Nu) * DO + 3 * (size_t)(Ni + Nu);
        int blocks = (int)((zf / 4 + 255) / 256) + 1;
        zero_k<<<blocks, 256>>>(msg_ui, zf);
    }

    // Prep split/transposed B images (merged)
    pre_w_k<<<128, 256>>>(W_ui_src, W_iu_tgt, B1hi, B1lo,
                          W_iu_src, W_ui_tgt, B2hi, B2lo);

    // Merged HMMA projections + fused node scores (2 halves per tile)
    {
        GA g1 = {x_user, B1hi, B1lo, sx_ui, tx_iu, a_ui, a_iu + DO, ss_ui, ts_iu, Nu};
        GA g2 = {x_item, B2hi, B2lo, sx_iu, tx_ui, a_iu, a_ui + DO, ss_iu, ts_ui, Ni};
        int nb1 = (Nu + 127) / 128;
        int nb2 = (Ni + 127) / 128;
        gemm_tc<<<2 * (nb1 + nb2), 256, SMEM_TOT>>>(g1, g2, nb1);
    }

    // Merged fused edge scatter
    {
        EA e1 = {edge_ui, edge_ui + Eui, ss_ui, ts_ui,
                 (const float4*)sx_ui, (float4*)msg_ui, den_ui, Eui};
        EA e2 = {edge_iu, edge_iu + Eiu, ss_iu, ts_iu,
                 (const float4*)sx_iu, (float4*)msg_iu, den_iu, Eiu};
        int nb1 = (Eui + 63) / 64;
        int nb2 = (Eiu + 63) / 64;
        edge_k<<<nb1 + nb2, 256>>>(e1, e2, nb1);
    }

    // Merged finalize
    {
        int n4u = Nu * 16, n4tot = (Nu + Ni) * 16;
        final_k<<<(n4tot + 255) / 256, 256>>>(
            (const float4*)tx_iu, (const float4*)msg_iu, den_iu,
            (const float4*)tx_ui, (const float4*)msg_ui, den_ui,
            (float4*)out, n4u, n4tot);
    }
}

// round 9
// speedup vs baseline: 1.0456x; 1.0456x over previous
#include <cuda_runtime.h>
#include <cuda_bf16.h>
#include <cstdint>
#include <cstddef>

#define DI 128
#define DO 64
#define NMAX 100000

// B image layout: [128 n][136 k-pitch] bf16 (272B row pitch)
#define BPITCH 136

// ---------------------------------------------------------------------------
// Scratch
// ---------------------------------------------------------------------------
__device__ __align__(16) float g_scratch[6 * (size_t)NMAX * DO + 6 * (size_t)NMAX];
__device__ __align__(16) __nv_bfloat16 g_B1hi[128 * BPITCH], g_B1lo[128 * BPITCH];
__device__ __align__(16) __nv_bfloat16 g_B2hi[128 * BPITCH], g_B2lo[128 * BPITCH];

__device__ __forceinline__ uint32_t smem_u32(const void* p) {
    uint32_t a;
    asm("{ .reg .u64 t; cvta.to.shared.u64 t, %1; cvt.u32.u64 %0, t; }"
        : "=r"(a) : "l"(p));
    return a;
}

__device__ __forceinline__ void ldm_x4(uint32_t* r, uint32_t addr) {
    asm volatile("ldmatrix.sync.aligned.m8n8.x4.shared.b16 {%0,%1,%2,%3}, [%4];"
                 : "=r"(r[0]), "=r"(r[1]), "=r"(r[2]), "=r"(r[3]) : "r"(addr));
}

__device__ __forceinline__ void mma_bf16(float* c, const uint32_t* a,
                                         uint32_t b0, uint32_t b1) {
    asm volatile("mma.sync.aligned.m16n8k16.row.col.f32.bf16.bf16.f32 "
                 "{%0,%1,%2,%3}, {%4,%5,%6,%7}, {%8,%9}, {%0,%1,%2,%3};"
                 : "+f"(c[0]), "+f"(c[1]), "+f"(c[2]), "+f"(c[3])
                 : "r"(a[0]), "r"(a[1]), "r"(a[2]), "r"(a[3]),
                   "r"(b0), "r"(b1));
}

__device__ __forceinline__ void split2(float x, float y, uint32_t& hi, uint32_t& lo) {
    __nv_bfloat162 h = __floats2bfloat162_rn(x, y);
    __nv_bfloat162 l = __floats2bfloat162_rn(x - __bfloat162float(h.x),
                                             y - __bfloat162float(h.y));
    hi = *(uint32_t*)&h;
    lo = *(uint32_t*)&l;
}

// SMEM layout (bytes). B tiles: 128 rows x 272B pitch
#define XPITCH 272
#define OFF_A    0                       // aA[64], aB[64] floats (512B)
#define OFF_BHI  512
#define OFF_BLO  (OFF_BHI + 128 * XPITCH)
#define SMEM_TOT (OFF_BLO + 128 * XPITCH)   // 70144

// ---------------------------------------------------------------------------
// Arg bundles for merged launches
// ---------------------------------------------------------------------------
struct GA {
    const float* X;
    const __nv_bfloat16* Bhi;
    const __nv_bfloat16* Blo;
    float* Ya; float* Yb;
    const float* aA; const float* aB;
    float* sA; float* sB;
    int N;
};
struct EA {
    const int* src; const int* tgt;
    const float* ss; const float* ts;
    const float4* sx4; float4* msg4; float* den;
    int E;
};

// ---------------------------------------------------------------------------
// Prep (merged): B[n][k] = Wa[k][n] (n<64) else Wb[k][n-64], split bf16 hi/lo.
// ---------------------------------------------------------------------------
__global__ void pre_w_k(const float* __restrict__ Wa1, const float* __restrict__ Wb1,
                        __nv_bfloat16* __restrict__ B1hi, __nv_bfloat16* __restrict__ B1lo,
                        const float* __restrict__ Wa2, const float* __restrict__ Wb2,
                        __nv_bfloat16* __restrict__ B2hi, __nv_bfloat16* __restrict__ B2lo) {
    int which = blockIdx.x >> 6;
    int idx = (blockIdx.x & 63) * 256 + threadIdx.x;
    const float* Wa = which ? Wa2 : Wa1;
    const float* Wb = which ? Wb2 : Wb1;
    __nv_bfloat16* Bhi = which ? B2hi : B1hi;
    __nv_bfloat16* Blo = which ? B2lo : B1lo;
    int n = idx >> 7, k = idx & 127;
    float w = (n < 64) ? Wa[k * 64 + n] : Wb[k * 64 + (n - 64)];
    __nv_bfloat16 hi = __float2bfloat16(w);
    __nv_bfloat16 lo = __float2bfloat16(w - __bfloat162float(hi));
    Bhi[n * BPITCH + k] = hi;
    Blo[n * BPITCH + k] = lo;
}

// ---------------------------------------------------------------------------
// zero kernel
// ---------------------------------------------------------------------------
__global__ void zero_k(float* __restrict__ p, size_t nf) {
    size_t i = ((size_t)blockIdx.x * blockDim.x + threadIdx.x) * 4;
    if (i + 4 <= nf) {
        *(float4*)(p + i) = make_float4(0.f, 0.f, 0.f, 0.f);
    } else {
        for (; i < nf; i++) p[i] = 0.f;
    }
}

// ---------------------------------------------------------------------------
// Merged HMMA GEMM, warp tiling 4M x 2N (exact R6 version — best known)
// ---------------------------------------------------------------------------
__global__ __launch_bounds__(256, 2)
void gemm_tc(GA g1, GA g2, int nb1)
{
    extern __shared__ char sm[];
    const uint32_t sb = smem_u32(sm);
    const int tid = threadIdx.x, wid = tid >> 5, lane = tid & 31;

    const bool first = blockIdx.x < (unsigned)nb1;
    const GA g = first ? g1 : g2;
    const int row0 = (first ? blockIdx.x : blockIdx.x - nb1) * 128;

    {
        const float4* bh = (const float4*)g.Bhi;
        const float4* bl = (const float4*)g.Blo;
        float4* sh = (float4*)(sm + OFF_BHI);
        float4* sl = (float4*)(sm + OFF_BLO);
        const int n4 = 128 * BPITCH * 2 / 16;   // 2176 float4
        for (int i = tid; i < n4; i += 256) {
            sh[i] = bh[i];
            sl[i] = bl[i];
        }
    }
    if (tid < 64)       ((float*)(sm + OFF_A))[tid] = __ldg(&g.aA[tid]);
    else if (tid < 128) ((float*)(sm + OFF_A))[tid] = __ldg(&g.aB[tid - 64]);

    const int wm = wid & 3, wn = wid >> 2;
    const int c0 = (lane & 3) * 2;

    const int rb = row0 + wm * 32 + (lane >> 2);
    int rows[4] = {rb, rb + 8, rb + 16, rb + 24};
    bool ok[4];
    const float* xp[4];
#pragma unroll
    for (int m = 0; m < 4; m++) {
        ok[m] = rows[m] < g.N;
        xp[m] = g.X + (size_t)(ok[m] ? rows[m] : 0) * DI + c0;
    }

    __syncthreads();

    float c[16][4];
#pragma unroll
    for (int j = 0; j < 16; j++)
#pragma unroll
        for (int q = 0; q < 4; q++) c[j][q] = 0.f;

    const int brow = (lane & 7) + ((lane >> 4) & 1) * 8;
    const int bkk  = ((lane >> 3) & 1) * 8;
    const uint32_t bbase = sb + (wn * 64 + brow) * XPITCH + bkk * 2;

#pragma unroll
    for (int s = 0; s < 8; s++) {
        const int ks = s * 16;
        float2 v[8];
#pragma unroll
        for (int m = 0; m < 4; m++) {
            v[m]     = ok[m] ? *(const float2*)(xp[m] + ks)     : make_float2(0.f, 0.f);
            v[m + 4] = ok[m] ? *(const float2*)(xp[m] + ks + 8) : make_float2(0.f, 0.f);
        }
        uint32_t ah0[4], al0[4], ah1[4], al1[4];
        split2(v[0].x, v[0].y, ah0[0], al0[0]);
        split2(v[1].x, v[1].y, ah0[1], al0[1]);
        split2(v[4].x, v[4].y, ah0[2], al0[2]);
        split2(v[5].x, v[5].y, ah0[3], al0[3]);
        split2(v[2].x, v[2].y, ah1[0], al1[0]);
        split2(v[3].x, v[3].y, ah1[1], al1[1]);
        split2(v[6].x, v[6].y, ah1[2], al1[2]);
        split2(v[7].x, v[7].y, ah1[3], al1[3]);

#pragma unroll
        for (int p = 0; p < 4; p++) {
            uint32_t bh[4], bl[4];
            uint32_t boff = (uint32_t)(p * 16) * XPITCH + ks * 2;
            ldm_x4(bh, bbase + OFF_BHI + boff);
            ldm_x4(bl, bbase + OFF_BLO + boff);
            mma_bf16(c[2 * p],     ah0, bh[0], bh[1]);
            mma_bf16(c[2 * p],     ah0, bl[0], bl[1]);
            mma_bf16(c[2 * p],     al0, bh[0], bh[1]);
            mma_bf16(c[2 * p + 1], ah0, bh[2], bh[3]);
            mma_bf16(c[2 * p + 1], ah0, bl[2], bl[3]);
            mma_bf16(c[2 * p + 1], al0, bh[2], bh[3]);
            mma_bf16(c[8 + 2 * p],     ah1, bh[0], bh[1]);
            mma_bf16(c[8 + 2 * p],     ah1, bl[0], bl[1]);
            mma_bf16(c[8 + 2 * p],     al1, bh[0], bh[1]);
            mma_bf16(c[8 + 2 * p + 1], ah1, bh[2], bh[3]);
            mma_bf16(c[8 + 2 * p + 1], ah1, bl[2], bl[3]);
            mma_bf16(c[8 + 2 * p + 1], al1, bh[2], bh[3]);
        }
    }

    const float* av = (const float*)(sm + OFF_A) + wn * 64;
    float* Y    = wn ? g.Yb : g.Ya;
    float* sOut = wn ? g.sB : g.sA;

    float sc[4] = {0.f, 0.f, 0.f, 0.f};
#pragma unroll
    for (int n = 0; n < 8; n++) {
        int col = n * 8 + c0;
        float a0 = av[col], a1 = av[col + 1];
        sc[0] += c[n][0] * a0 + c[n][1] * a1;
        sc[1] += c[n][2] * a0 + c[n][3] * a1;
        sc[2] += c[8 + n][0] * a0 + c[8 + n][1] * a1;
        sc[3] += c[8 + n][2] * a0 + c[8 + n][3] * a1;
        if (ok[0]) *(float2*)&Y[(size_t)rows[0] * DO + col] = make_float2(c[n][0], c[n][1]);
        if (ok[1]) *(float2*)&Y[(size_t)rows[1] * DO + col] = make_float2(c[n][2], c[n][3]);
        if (ok[2]) *(float2*)&Y[(size_t)rows[2] * DO + col] = make_float2(c[8 + n][0], c[8 + n][1]);
        if (ok[3]) *(float2*)&Y[(size_t)rows[3] * DO + col] = make_float2(c[8 + n][2], c[8 + n][3]);
    }
#pragma unroll
    for (int o = 1; o <= 2; o <<= 1) {
#pragma unroll
        for (int m = 0; m < 4; m++) sc[m] += __shfl_xor_sync(0xffffffffu, sc[m], o);
    }
    if ((lane & 3) == 0) {
#pragma unroll
        for (int m = 0; m < 4; m++)
            if (ok[m]) sOut[rows[m]] = sc[m];
    }
}

// ---------------------------------------------------------------------------
// Merged fused edge scatter: 16 lanes per edge, 2 edges per group,
// 32-reg budget -> 64 warps/SM (full occupancy). All loads issued as one
// independent front (MLP=6) before any dependent math/stores.
// ---------------------------------------------------------------------------
__global__ __launch_bounds__(256, 8) void edge_k(EA e1, EA e2, int nb1)
{
    const bool first = blockIdx.x < (unsigned)nb1;
    const EA a = first ? e1 : e2;
    const int bb = first ? blockIdx.x : blockIdx.x - nb1;

    int g = bb * 16 + (threadIdx.x >> 4);
    int lane = threadIdx.x & 15;
    int e0 = g * 2;
    if (e0 >= a.E) return;
    bool two = (e0 + 1) < a.E;
    int e1i = two ? e0 + 1 : e0;

    // Independent load front
    int s0 = __ldg(&a.src[e0]);
    int s1 = __ldg(&a.src[e1i]);
    int t0 = __ldg(&a.tgt[e0]);
    int t1 = __ldg(&a.tgt[e1i]);

    float ss0 = __ldg(&a.ss[s0]);
    float ss1 = __ldg(&a.ss[s1]);
    float ts0 = __ldg(&a.ts[t0]);
    float ts1 = __ldg(&a.ts[t1]);
    float4 v0 = __ldg(&a.sx4[(size_t)s0 * 16 + lane]);
    float4 v1 = __ldg(&a.sx4[(size_t)s1 * 16 + lane]);

    float sc0 = ss0 + ts0;
    float sc1 = ss1 + ts1;
    float at0 = expf(sc0 >= 0.f ? sc0 : 0.2f * sc0);
    float at1 = expf(sc1 >= 0.f ? sc1 : 0.2f * sc1);

    float4* p0 = &a.msg4[(size_t)t0 * 16 + lane];
    asm volatile("red.global.add.v4.f32 [%0], {%1,%2,%3,%4};"
                 :: "l"(p0), "f"(v0.x * at0), "f"(v0.y * at0),
                    "f"(v0.z * at0), "f"(v0.w * at0) : "memory");
    if (two) {
        float4* p1 = &a.msg4[(size_t)t1 * 16 + lane];
        asm volatile("red.global.add.v4.f32 [%0], {%1,%2,%3,%4};"
                     :: "l"(p1), "f"(v1.x * at1), "f"(v1.y * at1),
                        "f"(v1.z * at1), "f"(v1.w * at1) : "memory");
    }
    if (lane == 0) {
        atomicAdd(&a.den[t0], at0);
        if (two) atomicAdd(&a.den[t1], at1);
    }
}

// ---------------------------------------------------------------------------
// Merged finalize: out = tx + msg / (den + eps)
// ---------------------------------------------------------------------------
__global__ __launch_bounds__(256) void final_k(
    const float4* __restrict__ txu, const float4* __restrict__ msgu,
    const float* __restrict__ denu,
    const float4* __restrict__ txi, const float4* __restrict__ msgi,
    const float* __restrict__ deni,
    float4* __restrict__ out, int n4u, int n4tot)
{
    int i = blockIdx.x * blockDim.x + threadIdx.x;
    if (i >= n4tot) return;
    const float4* txp; const float4* msg; const float* den;
    int li;
    if (i < n4u) { txp = txu; msg = msgu; den = denu; li = i; }
    else         { txp = txi; msg = msgi; den = deni; li = i - n4u; }
    int node = li >> 4;
    float inv = 1.f / (den[node] + 1e-6f);
    float4 m = msg[li];
    float4 t = txp[li];
    out[i] = make_float4(t.x + m.x * inv, t.y + m.y * inv,
                         t.z + m.z * inv, t.w + m.w * inv);
}

// ---------------------------------------------------------------------------
extern "C" void kernel_launch(void* const* d_in, const int* in_sizes, int n_in,
                              void* d_out, int out_size)
{
    const float* x_user   = (const float*)d_in[0];
    const float* x_item   = (const float*)d_in[1];
    const float* W_ui_src = (const float*)d_in[2];
    const float* W_ui_tgt = (const float*)d_in[3];
    const float* W_iu_src = (const float*)d_in[4];
    const float* W_iu_tgt = (const float*)d_in[5];
    const float* a_ui     = (const float*)d_in[6];
    const float* a_iu     = (const float*)d_in[7];
    const int*   edge_ui  = (const int*)d_in[8];
    const int*   edge_iu  = (const int*)d_in[9];
    float* out = (float*)d_out;

    const int Nu  = in_sizes[0] / DI;
    const int Ni  = in_sizes[1] / DI;
    const int Eui = in_sizes[8] / 2;
    const int Eiu = in_sizes[9] / 2;

    float* base = nullptr;
    cudaGetSymbolAddress((void**)&base, g_scratch);
    __nv_bfloat16 *B1hi, *B1lo, *B2hi, *B2lo;
    cudaGetSymbolAddress((void**)&B1hi, g_B1hi);
    cudaGetSymbolAddress((void**)&B1lo, g_B1lo);
    cudaGetSymbolAddress((void**)&B2hi, g_B2hi);
    cudaGetSymbolAddress((void**)&B2lo, g_B2lo);

    float* s = base;
    float* sx_ui  = s; s += (size_t)Nu * DO;
    float* tx_iu  = s; s += (size_t)Nu * DO;
    float* sx_iu  = s; s += (size_t)Ni * DO;
    float* tx_ui  = s; s += (size_t)Ni * DO;
    float* msg_ui = s; s += (size_t)Ni * DO;
    float* msg_iu = s; s += (size_t)Nu * DO;
    float* den_ui = s; s += Ni;
    float* den_iu = s; s += Nu;
    float* ss_ui  = s; s += Nu;
    float* ts_ui  = s; s += Ni;
    float* ss_iu  = s; s += Ni;
    float* ts_iu  = s; s += Nu;

    cudaFuncSetAttribute(gemm_tc, cudaFuncAttributeMaxDynamicSharedMemorySize, SMEM_TOT);

    // Zero msg + den (contiguous region starting at msg_ui)
    {
        size_t zf = (size_t)(Ni + Nu) * DO + (size_t)Ni + (size_t)Nu;
        int blocks = (int)((zf / 4 + 255) / 256) + 1;
        zero_k<<<blocks, 256>>>(msg_ui, zf);
    }

    // Prep split/transposed B images (merged)
    pre_w_k<<<128, 256>>>(W_ui_src, W_iu_tgt, B1hi, B1lo,
                          W_iu_src, W_ui_tgt, B2hi, B2lo);

    // Merged HMMA projections + fused node scores (R6 config)
    {
        GA g1 = {x_user, B1hi, B1lo, sx_ui, tx_iu, a_ui, a_iu + DO, ss_ui, ts_iu, Nu};
        GA g2 = {x_item, B2hi, B2lo, sx_iu, tx_ui, a_iu, a_ui + DO, ss_iu, ts_ui, Ni};
        int nb1 = (Nu + 127) / 128;
        int nb2 = (Ni + 127) / 128;
        gemm_tc<<<nb1 + nb2, 256, SMEM_TOT>>>(g1, g2, nb1);
    }

    // Merged fused edge scatter (2 edges/group, full occupancy)
    {
        EA e1 = {edge_ui, edge_ui + Eui, ss_ui, ts_ui,
                 (const float4*)sx_ui, (float4*)msg_ui, den_ui, Eui};
        EA e2 = {edge_iu, edge_iu + Eiu, ss_iu, ts_iu,
                 (const float4*)sx_iu, (float4*)msg_iu, den_iu, Eiu};
        int nb1 = (Eui + 31) / 32;
        int nb2 = (Eiu + 31) / 32;
        edge_k<<<nb1 + nb2, 256>>>(e1, e2, nb1);
    }

    // Merged finalize
    {
        int n4u = Nu * 16, n4tot = (Nu + Ni) * 16;
        final_k<<<(n4tot + 255) / 256, 256>>>(
            (const float4*)tx_iu, (const float4*)msg_iu, den_iu,
            (const float4*)tx_ui, (const float4*)msg_ui, den_ui,
            (float4*)out, n4u, n4tot);
    }
}

// round 10
// speedup vs baseline: 1.0827x; 1.0355x over previous
#include <cuda_runtime.h>
#include <cuda_bf16.h>
#include <cuda_fp16.h>
#include <cstdint>
#include <cstddef>

#define DI 128
#define DO 64
#define NMAX 100000

// B image layout: [128 n][136 k-pitch] bf16 (272B row pitch)
#define BPITCH 136

// ---------------------------------------------------------------------------
// Scratch
// ---------------------------------------------------------------------------
__device__ __align__(16) float g_scratch[6 * (size_t)NMAX * DO + 6 * (size_t)NMAX];
__device__ __align__(16) __nv_bfloat16 g_B1hi[128 * BPITCH], g_B1lo[128 * BPITCH];
__device__ __align__(16) __nv_bfloat16 g_B2hi[128 * BPITCH], g_B2lo[128 * BPITCH];

__device__ __forceinline__ uint32_t smem_u32(const void* p) {
    uint32_t a;
    asm("{ .reg .u64 t; cvta.to.shared.u64 t, %1; cvt.u32.u64 %0, t; }"
        : "=r"(a) : "l"(p));
    return a;
}

__device__ __forceinline__ void ldm_x4(uint32_t* r, uint32_t addr) {
    asm volatile("ldmatrix.sync.aligned.m8n8.x4.shared.b16 {%0,%1,%2,%3}, [%4];"
                 : "=r"(r[0]), "=r"(r[1]), "=r"(r[2]), "=r"(r[3]) : "r"(addr));
}

__device__ __forceinline__ void mma_bf16(float* c, const uint32_t* a,
                                         uint32_t b0, uint32_t b1) {
    asm volatile("mma.sync.aligned.m16n8k16.row.col.f32.bf16.bf16.f32 "
                 "{%0,%1,%2,%3}, {%4,%5,%6,%7}, {%8,%9}, {%0,%1,%2,%3};"
                 : "+f"(c[0]), "+f"(c[1]), "+f"(c[2]), "+f"(c[3])
                 : "r"(a[0]), "r"(a[1]), "r"(a[2]), "r"(a[3]),
                   "r"(b0), "r"(b1));
}

__device__ __forceinline__ void split2(float x, float y, uint32_t& hi, uint32_t& lo) {
    __nv_bfloat162 h = __floats2bfloat162_rn(x, y);
    __nv_bfloat162 l = __floats2bfloat162_rn(x - __bfloat162float(h.x),
                                             y - __bfloat162float(h.y));
    hi = *(uint32_t*)&h;
    lo = *(uint32_t*)&l;
}

// SMEM layout (bytes). B tiles: 128 rows x 272B pitch
#define XPITCH 272
#define OFF_A    0                       // aA[64], aB[64] floats (512B)
#define OFF_BHI  512
#define OFF_BLO  (OFF_BHI + 128 * XPITCH)
#define SMEM_TOT (OFF_BLO + 128 * XPITCH)   // 70144

// ---------------------------------------------------------------------------
// Arg bundles for merged launches
// ---------------------------------------------------------------------------
struct GA {
    const float* X;
    const __nv_bfloat16* Bhi;
    const __nv_bfloat16* Blo;
    __half* Yh;        // src-projection output (fp16, edge-gather only)
    float*  Yf;        // tgt-projection output (fp32)
    const float* aA; const float* aB;
    float* sA; float* sB;
    int N;
};
struct EA {
    const int* src; const int* tgt;
    const float* ss; const float* ts;
    const uint2* sxh;          // fp16 features: 16 x uint2 (64 halves) per node
    float4* msg4; float* den;
    int E;
};

// ---------------------------------------------------------------------------
// Prep (merged): B[n][k] = Wa[k][n] (n<64) else Wb[k][n-64], split bf16 hi/lo.
// ---------------------------------------------------------------------------
__global__ void pre_w_k(const float* __restrict__ Wa1, const float* __restrict__ Wb1,
                        __nv_bfloat16* __restrict__ B1hi, __nv_bfloat16* __restrict__ B1lo,
                        const float* __restrict__ Wa2, const float* __restrict__ Wb2,
                        __nv_bfloat16* __restrict__ B2hi, __nv_bfloat16* __restrict__ B2lo) {
    int which = blockIdx.x >> 6;
    int idx = (blockIdx.x & 63) * 256 + threadIdx.x;
    const float* Wa = which ? Wa2 : Wa1;
    const float* Wb = which ? Wb2 : Wb1;
    __nv_bfloat16* Bhi = which ? B2hi : B1hi;
    __nv_bfloat16* Blo = which ? B2lo : B1lo;
    int n = idx >> 7, k = idx & 127;
    float w = (n < 64) ? Wa[k * 64 + n] : Wb[k * 64 + (n - 64)];
    __nv_bfloat16 hi = __float2bfloat16(w);
    __nv_bfloat16 lo = __float2bfloat16(w - __bfloat162float(hi));
    Bhi[n * BPITCH + k] = hi;
    Blo[n * BPITCH + k] = lo;
}

// ---------------------------------------------------------------------------
// zero kernel
// ---------------------------------------------------------------------------
__global__ void zero_k(float* __restrict__ p, size_t nf) {
    size_t i = ((size_t)blockIdx.x * blockDim.x + threadIdx.x) * 4;
    if (i + 4 <= nf) {
        *(float4*)(p + i) = make_float4(0.f, 0.f, 0.f, 0.f);
    } else {
        for (; i < nf; i++) p[i] = 0.f;
    }
}

// ---------------------------------------------------------------------------
// Merged HMMA GEMM, warp tiling 4M x 2N (R6 mainloop).
// wn==0 warps write the src-projection as fp16 (Yh) + score A;
// wn==1 warps write the tgt-projection as fp32 (Yf) + score B.
// Scores computed from fp32 accumulators BEFORE fp16 rounding.
// ---------------------------------------------------------------------------
__global__ __launch_bounds__(256, 2)
void gemm_tc(GA g1, GA g2, int nb1)
{
    extern __shared__ char sm[];
    const uint32_t sb = smem_u32(sm);
    const int tid = threadIdx.x, wid = tid >> 5, lane = tid & 31;

    const bool first = blockIdx.x < (unsigned)nb1;
    const GA g = first ? g1 : g2;
    const int row0 = (first ? blockIdx.x : blockIdx.x - nb1) * 128;

    {
        const float4* bh = (const float4*)g.Bhi;
        const float4* bl = (const float4*)g.Blo;
        float4* sh = (float4*)(sm + OFF_BHI);
        float4* sl = (float4*)(sm + OFF_BLO);
        const int n4 = 128 * BPITCH * 2 / 16;   // 2176 float4
        for (int i = tid; i < n4; i += 256) {
            sh[i] = bh[i];
            sl[i] = bl[i];
        }
    }
    if (tid < 64)       ((float*)(sm + OFF_A))[tid] = __ldg(&g.aA[tid]);
    else if (tid < 128) ((float*)(sm + OFF_A))[tid] = __ldg(&g.aB[tid - 64]);

    const int wm = wid & 3, wn = wid >> 2;
    const int c0 = (lane & 3) * 2;

    const int rb = row0 + wm * 32 + (lane >> 2);
    int rows[4] = {rb, rb + 8, rb + 16, rb + 24};
    bool ok[4];
    const float* xp[4];
#pragma unroll
    for (int m = 0; m < 4; m++) {
        ok[m] = rows[m] < g.N;
        xp[m] = g.X + (size_t)(ok[m] ? rows[m] : 0) * DI + c0;
    }

    __syncthreads();

    float c[16][4];
#pragma unroll
    for (int j = 0; j < 16; j++)
#pragma unroll
        for (int q = 0; q < 4; q++) c[j][q] = 0.f;

    const int brow = (lane & 7) + ((lane >> 4) & 1) * 8;
    const int bkk  = ((lane >> 3) & 1) * 8;
    const uint32_t bbase = sb + (wn * 64 + brow) * XPITCH + bkk * 2;

#pragma unroll
    for (int s = 0; s < 8; s++) {
        const int ks = s * 16;
        float2 v[8];
#pragma unroll
        for (int m = 0; m < 4; m++) {
            v[m]     = ok[m] ? *(const float2*)(xp[m] + ks)     : make_float2(0.f, 0.f);
            v[m + 4] = ok[m] ? *(const float2*)(xp[m] + ks + 8) : make_float2(0.f, 0.f);
        }
        uint32_t ah0[4], al0[4], ah1[4], al1[4];
        split2(v[0].x, v[0].y, ah0[0], al0[0]);
        split2(v[1].x, v[1].y, ah0[1], al0[1]);
        split2(v[4].x, v[4].y, ah0[2], al0[2]);
        split2(v[5].x, v[5].y, ah0[3], al0[3]);
        split2(v[2].x, v[2].y, ah1[0], al1[0]);
        split2(v[3].x, v[3].y, ah1[1], al1[1]);
        split2(v[6].x, v[6].y, ah1[2], al1[2]);
        split2(v[7].x, v[7].y, ah1[3], al1[3]);

#pragma unroll
        for (int p = 0; p < 4; p++) {
            uint32_t bh[4], bl[4];
            uint32_t boff = (uint32_t)(p * 16) * XPITCH + ks * 2;
            ldm_x4(bh, bbase + OFF_BHI + boff);
            ldm_x4(bl, bbase + OFF_BLO + boff);
            mma_bf16(c[2 * p],     ah0, bh[0], bh[1]);
            mma_bf16(c[2 * p],     ah0, bl[0], bl[1]);
            mma_bf16(c[2 * p],     al0, bh[0], bh[1]);
            mma_bf16(c[2 * p + 1], ah0, bh[2], bh[3]);
            mma_bf16(c[2 * p + 1], ah0, bl[2], bl[3]);
            mma_bf16(c[2 * p + 1], al0, bh[2], bh[3]);
            mma_bf16(c[8 + 2 * p],     ah1, bh[0], bh[1]);
            mma_bf16(c[8 + 2 * p],     ah1, bl[0], bl[1]);
            mma_bf16(c[8 + 2 * p],     al1, bh[0], bh[1]);
            mma_bf16(c[8 + 2 * p + 1], ah1, bh[2], bh[3]);
            mma_bf16(c[8 + 2 * p + 1], ah1, bl[2], bl[3]);
            mma_bf16(c[8 + 2 * p + 1], al1, bh[2], bh[3]);
        }
    }

    const float* av = (const float*)(sm + OFF_A) + wn * 64;
    float* sOut = wn ? g.sB : g.sA;

    float sc[4] = {0.f, 0.f, 0.f, 0.f};
#pragma unroll
    for (int n = 0; n < 8; n++) {
        int col = n * 8 + c0;
        float a0 = av[col], a1 = av[col + 1];
        sc[0] += c[n][0] * a0 + c[n][1] * a1;
        sc[1] += c[n][2] * a0 + c[n][3] * a1;
        sc[2] += c[8 + n][0] * a0 + c[8 + n][1] * a1;
        sc[3] += c[8 + n][2] * a0 + c[8 + n][3] * a1;
        if (wn == 0) {
            // fp16 stores (src projection, edge-gather consumer)
            if (ok[0]) *(__half2*)&g.Yh[(size_t)rows[0] * DO + col] =
                __floats2half2_rn(c[n][0], c[n][1]);
            if (ok[1]) *(__half2*)&g.Yh[(size_t)rows[1] * DO + col] =
                __floats2half2_rn(c[n][2], c[n][3]);
            if (ok[2]) *(__half2*)&g.Yh[(size_t)rows[2] * DO + col] =
                __floats2half2_rn(c[8 + n][0], c[8 + n][1]);
            if (ok[3]) *(__half2*)&g.Yh[(size_t)rows[3] * DO + col] =
                __floats2half2_rn(c[8 + n][2], c[8 + n][3]);
        } else {
            // fp32 stores (tgt projection, finalize consumer)
            if (ok[0]) *(float2*)&g.Yf[(size_t)rows[0] * DO + col] = make_float2(c[n][0], c[n][1]);
            if (ok[1]) *(float2*)&g.Yf[(size_t)rows[1] * DO + col] = make_float2(c[n][2], c[n][3]);
            if (ok[2]) *(float2*)&g.Yf[(size_t)rows[2] * DO + col] = make_float2(c[8 + n][0], c[8 + n][1]);
            if (ok[3]) *(float2*)&g.Yf[(size_t)rows[3] * DO + col] = make_float2(c[8 + n][2], c[8 + n][3]);
        }
    }
#pragma unroll
    for (int o = 1; o <= 2; o <<= 1) {
#pragma unroll
        for (int m = 0; m < 4; m++) sc[m] += __shfl_xor_sync(0xffffffffu, sc[m], o);
    }
    if ((lane & 3) == 0) {
#pragma unroll
        for (int m = 0; m < 4; m++)
            if (ok[m]) sOut[rows[m]] = sc[m];
    }
}

// ---------------------------------------------------------------------------
// Merged fused edge scatter: 16 lanes per edge, 2 edges per group.
// fp16 feature gather (8B/lane), fp32 red.v4 message accumulation.
// ---------------------------------------------------------------------------
__global__ __launch_bounds__(256, 8) void edge_k(EA e1, EA e2, int nb1)
{
    const bool first = blockIdx.x < (unsigned)nb1;
    const EA a = first ? e1 : e2;
    const int bb = first ? blockIdx.x : blockIdx.x - nb1;

    int g = bb * 16 + (threadIdx.x >> 4);
    int lane = threadIdx.x & 15;
    int e0 = g * 2;
    if (e0 >= a.E) return;
    bool two = (e0 + 1) < a.E;
    int e1i = two ? e0 + 1 : e0;

    // Independent load front
    int s0 = __ldg(&a.src[e0]);
    int s1 = __ldg(&a.src[e1i]);
    int t0 = __ldg(&a.tgt[e0]);
    int t1 = __ldg(&a.tgt[e1i]);

    float ss0 = __ldg(&a.ss[s0]);
    float ss1 = __ldg(&a.ss[s1]);
    float ts0 = __ldg(&a.ts[t0]);
    float ts1 = __ldg(&a.ts[t1]);
    uint2 u0 = __ldg(&a.sxh[(size_t)s0 * 16 + lane]);
    uint2 u1 = __ldg(&a.sxh[(size_t)s1 * 16 + lane]);

    float sc0 = ss0 + ts0;
    float sc1 = ss1 + ts1;
    float at0 = expf(sc0 >= 0.f ? sc0 : 0.2f * sc0);
    float at1 = expf(sc1 >= 0.f ? sc1 : 0.2f * sc1);

    float2 f00 = __half22float2(*(__half2*)&u0.x);
    float2 f01 = __half22float2(*(__half2*)&u0.y);
    float2 f10 = __half22float2(*(__half2*)&u1.x);
    float2 f11 = __half22float2(*(__half2*)&u1.y);

    float4* p0 = &a.msg4[(size_t)t0 * 16 + lane];
    asm volatile("red.global.add.v4.f32 [%0], {%1,%2,%3,%4};"
                 :: "l"(p0), "f"(f00.x * at0), "f"(f00.y * at0),
                    "f"(f01.x * at0), "f"(f01.y * at0) : "memory");
    if (two) {
        float4* p1 = &a.msg4[(size_t)t1 * 16 + lane];
        asm volatile("red.global.add.v4.f32 [%0], {%1,%2,%3,%4};"
                     :: "l"(p1), "f"(f10.x * at1), "f"(f10.y * at1),
                        "f"(f11.x * at1), "f"(f11.y * at1) : "memory");
    }
    if (lane == 0) {
        atomicAdd(&a.den[t0], at0);
        if (two) atomicAdd(&a.den[t1], at1);
    }
}

// ---------------------------------------------------------------------------
// Merged finalize: out = tx + msg / (den + eps)
// ---------------------------------------------------------------------------
__global__ __launch_bounds__(256) void final_k(
    const float4* __restrict__ txu, const float4* __restrict__ msgu,
    const float* __restrict__ denu,
    const float4* __restrict__ txi, const float4* __restrict__ msgi,
    const float* __restrict__ deni,
    float4* __restrict__ out, int n4u, int n4tot)
{
    int i = blockIdx.x * blockDim.x + threadIdx.x;
    if (i >= n4tot) return;
    const float4* txp; const float4* msg; const float* den;
    int li;
    if (i < n4u) { txp = txu; msg = msgu; den = denu; li = i; }
    else         { txp = txi; msg = msgi; den = deni; li = i - n4u; }
    int node = li >> 4;
    float inv = 1.f / (den[node] + 1e-6f);
    float4 m = msg[li];
    float4 t = txp[li];
    out[i] = make_float4(t.x + m.x * inv, t.y + m.y * inv,
                         t.z + m.z * inv, t.w + m.w * inv);
}

// ---------------------------------------------------------------------------
extern "C" void kernel_launch(void* const* d_in, const int* in_sizes, int n_in,
                              void* d_out, int out_size)
{
    const float* x_user   = (const float*)d_in[0];
    const float* x_item   = (const float*)d_in[1];
    const float* W_ui_src = (const float*)d_in[2];
    const float* W_ui_tgt = (const float*)d_in[3];
    const float* W_iu_src = (const float*)d_in[4];
    const float* W_iu_tgt = (const float*)d_in[5];
    const float* a_ui     = (const float*)d_in[6];
    const float* a_iu     = (const float*)d_in[7];
    const int*   edge_ui  = (const int*)d_in[8];
    const int*   edge_iu  = (const int*)d_in[9];
    float* out = (float*)d_out;

    const int Nu  = in_sizes[0] / DI;
    const int Ni  = in_sizes[1] / DI;
    const int Eui = in_sizes[8] / 2;
    const int Eiu = in_sizes[9] / 2;

    float* base = nullptr;
    cudaGetSymbolAddress((void**)&base, g_scratch);
    __nv_bfloat16 *B1hi, *B1lo, *B2hi, *B2lo;
    cudaGetSymbolAddress((void**)&B1hi, g_B1hi);
    cudaGetSymbolAddress((void**)&B1lo, g_B1lo);
    cudaGetSymbolAddress((void**)&B2hi, g_B2hi);
    cudaGetSymbolAddress((void**)&B2lo, g_B2lo);

    float* s = base;
    __half* sxh_ui = (__half*)s; s += (size_t)Nu * DO / 2;   // fp16: Nu*64 halves
    float*  tx_iu  = s;          s += (size_t)Nu * DO;
    __half* sxh_iu = (__half*)s; s += (size_t)Ni * DO / 2;
    float*  tx_ui  = s;          s += (size_t)Ni * DO;
    float*  msg_ui = s;          s += (size_t)Ni * DO;
    float*  msg_iu = s;          s += (size_t)Nu * DO;
    float*  den_ui = s;          s += Ni;
    float*  den_iu = s;          s += Nu;
    float*  ss_ui  = s;          s += Nu;
    float*  ts_ui  = s;          s += Ni;
    float*  ss_iu  = s;          s += Ni;
    float*  ts_iu  = s;          s += Nu;

    cudaFuncSetAttribute(gemm_tc, cudaFuncAttributeMaxDynamicSharedMemorySize, SMEM_TOT);

    // Zero msg + den (contiguous region starting at msg_ui)
    {
        size_t zf = (size_t)(Ni + Nu) * DO + (size_t)Ni + (size_t)Nu;
        int blocks = (int)((zf / 4 + 255) / 256) + 1;
        zero_k<<<blocks, 256>>>(msg_ui, zf);
    }

    // Prep split/transposed B images (merged)
    pre_w_k<<<128, 256>>>(W_ui_src, W_iu_tgt, B1hi, B1lo,
                          W_iu_src, W_ui_tgt, B2hi, B2lo);

    // Merged HMMA projections + fused node scores
    {
        GA g1 = {x_user, B1hi, B1lo, sxh_ui, tx_iu, a_ui, a_iu + DO, ss_ui, ts_iu, Nu};
        GA g2 = {x_item, B2hi, B2lo, sxh_iu, tx_ui, a_iu, a_ui + DO, ss_iu, ts_ui, Ni};
        int nb1 = (Nu + 127) / 128;
        int nb2 = (Ni + 127) / 128;
        gemm_tc<<<nb1 + nb2, 256, SMEM_TOT>>>(g1, g2, nb1);
    }

    // Merged fused edge scatter (fp16 gather)
    {
        EA e1 = {edge_ui, edge_ui + Eui, ss_ui, ts_ui,
                 (const uint2*)sxh_ui, (float4*)msg_ui, den_ui, Eui};
        EA e2 = {edge_iu, edge_iu + Eiu, ss_iu, ts_iu,
                 (const uint2*)sxh_iu, (float4*)msg_iu, den_iu, Eiu};
        int nb1 = (Eui + 31) / 32;
        int nb2 = (Eiu + 31) / 32;
        edge_k<<<nb1 + nb2, 256>>>(e1, e2, nb1);
    }

    // Merged finalize
    {
        int n4u = Nu * 16, n4tot = (Nu + Ni) * 16;
        final_k<<<(n4tot + 255) / 256, 256>>>(
            (const float4*)tx_iu, (const float4*)msg_iu, den_iu,
            (const float4*)tx_ui, (const float4*)msg_ui, den_ui,
            (float4*)out, n4u, n4tot);
    }
}